// round 1
// baseline (speedup 1.0000x reference)
#include <cuda_runtime.h>
#include <math.h>

#define TM       128     // rows per CTA
#define KT       16      // K chunk for W2 staging
#define NCHUNK   16      // 256 / KT
#define NTHREADS 512

// ---- shared memory layout (in floats) ----
#define OFF_H1T   0                         // h1^T [256][128]
#define OFF_WBUF  (256*128)                 // W2 double buffer [2][KT][256]
#define OFF_W1S   (OFF_WBUF + 2*KT*256)     // W1 [3][256]
#define OFF_B1S   (OFF_W1S + 3*256)         // b1 [256]
#define OFF_B2S   (OFF_B1S + 256)           // b2 [256]
#define OFF_W3S   (OFF_B2S + 256)           // W3 [256][3]
#define OFF_B3S   (OFF_W3S + 256*3)         // b3 [4]
#define OFF_RS    (OFF_B3S + 4)             // r  [128][3]
#define OFF_XS    (OFF_RS + 128*3)          // x tile [128*9]
#define SMEM_FLOATS (OFF_XS + 128*9)
#define SMEM_BYTES  (SMEM_FLOATS * 4)

__global__ __launch_bounds__(NTHREADS, 1)
void nn_adiab_kernel(const float* __restrict__ x,
                     const float* __restrict__ W1,
                     const float* __restrict__ b1,
                     const float* __restrict__ W2,
                     const float* __restrict__ b2,
                     const float* __restrict__ W3,
                     const float* __restrict__ b3,
                     float* __restrict__ out,
                     int B)
{
    extern __shared__ float sm[];
    const int tid = threadIdx.x;
    const int xg  = tid & 31;   // column group (lane)
    const int yg  = tid >> 5;   // row group == warp id (all lanes share yg)
    const int row0 = blockIdx.x * TM;

    // ---- load small weights into smem ----
    for (int i = tid; i < 3*256; i += NTHREADS) sm[OFF_W1S + i] = W1[i];
    for (int i = tid; i < 256;   i += NTHREADS) sm[OFF_B1S + i] = b1[i];
    for (int i = tid; i < 256;   i += NTHREADS) sm[OFF_B2S + i] = b2[i];
    for (int i = tid; i < 256*3; i += NTHREADS) sm[OFF_W3S + i] = W3[i];
    if (tid < 3) sm[OFF_B3S + tid] = b3[tid];

    // ---- coalesced x tile load (zero-fill out-of-range rows) ----
    for (int i = tid; i < TM*9; i += NTHREADS) {
        int r = row0 + i / 9;
        sm[OFF_XS + i] = (r < B) ? x[(size_t)row0 * 9 + i] : 0.f;
    }
    __syncthreads();

    // ---- pairwise distances: r[m][0..2] for pairs (0,1),(0,2),(1,2) ----
    if (tid < TM) {
        const float* p = sm + OFF_XS + tid * 9;
        float ax = p[0], ay = p[1], az = p[2];
        float bx = p[3], by = p[4], bz = p[5];
        float cx = p[6], cy = p[7], cz = p[8];
        float d0x = ax-bx, d0y = ay-by, d0z = az-bz;
        float d1x = ax-cx, d1y = ay-cy, d1z = az-cz;
        float d2x = bx-cx, d2y = by-cy, d2z = bz-cz;
        sm[OFF_RS + tid*3 + 0] = sqrtf(d0x*d0x + d0y*d0y + d0z*d0z);
        sm[OFF_RS + tid*3 + 1] = sqrtf(d1x*d1x + d1y*d1y + d1z*d1z);
        sm[OFF_RS + tid*3 + 2] = sqrtf(d2x*d2x + d2y*d2y + d2z*d2z);
    }
    __syncthreads();

    // ---- layer 1: h1^T[k][m] = relu(b1[k] + sum_p r[m][p] * W1[p][k]) ----
    for (int idx = tid; idx < 256 * TM; idx += NTHREADS) {
        int m = idx & (TM - 1);
        int k = idx >> 7;
        float v = sm[OFF_B1S + k];
        v = fmaf(sm[OFF_RS + m*3 + 0], sm[OFF_W1S +       k], v);
        v = fmaf(sm[OFF_RS + m*3 + 1], sm[OFF_W1S + 256 + k], v);
        v = fmaf(sm[OFF_RS + m*3 + 2], sm[OFF_W1S + 512 + k], v);
        sm[OFF_H1T + k*TM + m] = fmaxf(v, 0.f);
    }

    // ---- main GEMM: z2[128][256] = h1[128][256] @ W2[256][256] ----
    float acc[8][8];
    #pragma unroll
    for (int i = 0; i < 8; i++)
        #pragma unroll
        for (int j = 0; j < 8; j++) acc[i][j] = 0.f;

    // preload W2 chunk 0 (each thread: 2 float4 = 8 floats of the 16x256 chunk)
    float4 pfA = ((const float4*)W2)[tid];
    float4 pfB = ((const float4*)W2)[tid + NTHREADS];
    ((float4*)(sm + OFF_WBUF))[tid]            = pfA;
    ((float4*)(sm + OFF_WBUF))[tid + NTHREADS] = pfB;
    __syncthreads();

    for (int c = 0; c < NCHUNK; c++) {
        // prefetch next chunk from gmem (L2-hot after wave 1)
        if (c + 1 < NCHUNK) {
            const float4* src = (const float4*)(W2 + (size_t)(c + 1) * KT * 256);
            pfA = src[tid];
            pfB = src[tid + NTHREADS];
        }
        const float* Bb = sm + OFF_WBUF + (c & 1) * (KT * 256);
        const float* Ab = sm + OFF_H1T + c * (KT * TM);
        #pragma unroll
        for (int kl = 0; kl < KT; kl++) {
            const float* ar = Ab + kl * TM;
            const float* br = Bb + kl * 256;
            float4 a0 = *(const float4*)(ar + 4*yg);        // broadcast across warp
            float4 a1 = *(const float4*)(ar + 64 + 4*yg);
            float4 b0 = *(const float4*)(br + 4*xg);        // conflict-free
            float4 b1v = *(const float4*)(br + 128 + 4*xg);
            float av[8] = {a0.x,a0.y,a0.z,a0.w, a1.x,a1.y,a1.z,a1.w};
            float bv[8] = {b0.x,b0.y,b0.z,b0.w, b1v.x,b1v.y,b1v.z,b1v.w};
            #pragma unroll
            for (int i = 0; i < 8; i++)
                #pragma unroll
                for (int j = 0; j < 8; j++)
                    acc[i][j] = fmaf(av[i], bv[j], acc[i][j]);
        }
        __syncthreads();
        if (c + 1 < NCHUNK) {
            float4* dst = (float4*)(sm + OFF_WBUF + ((c + 1) & 1) * (KT * 256));
            dst[tid]            = pfA;
            dst[tid + NTHREADS] = pfB;
            __syncthreads();
        }
    }

    // ---- layer 3 partials directly from registers: p[i][j3] = sum_n relu(z2+b2)*W3[n][j3]
    float p[8][3];
    #pragma unroll
    for (int i = 0; i < 8; i++) { p[i][0]=0.f; p[i][1]=0.f; p[i][2]=0.f; }

    #pragma unroll
    for (int j = 0; j < 8; j++) {
        int n = (j < 4) ? (xg*4 + j) : (128 + xg*4 + (j - 4));
        float bn  = sm[OFF_B2S + n];
        float w30 = sm[OFF_W3S + n*3 + 0];
        float w31 = sm[OFF_W3S + n*3 + 1];
        float w32 = sm[OFF_W3S + n*3 + 2];
        #pragma unroll
        for (int i = 0; i < 8; i++) {
            float h = fmaxf(acc[i][j] + bn, 0.f);
            p[i][0] = fmaf(h, w30, p[i][0]);
            p[i][1] = fmaf(h, w31, p[i][1]);
            p[i][2] = fmaf(h, w32, p[i][2]);
        }
    }

    // ---- warp butterfly reduction: each warp spans all 256 N-cols ----
    #pragma unroll
    for (int off = 16; off > 0; off >>= 1) {
        #pragma unroll
        for (int i = 0; i < 8; i++) {
            p[i][0] += __shfl_xor_sync(0xffffffffu, p[i][0], off);
            p[i][1] += __shfl_xor_sync(0xffffffffu, p[i][1], off);
            p[i][2] += __shfl_xor_sync(0xffffffffu, p[i][2], off);
        }
    }

    // ---- lane 0: eigen epilogue + store (8 rows per warp) ----
    if (xg == 0) {
        float bb0 = sm[OFF_B3S + 0], bb1 = sm[OFF_B3S + 1], bb2 = sm[OFF_B3S + 2];
        #pragma unroll
        for (int i = 0; i < 8; i++) {
            int m = (i < 4) ? (yg*4 + i) : (64 + yg*4 + (i - 4));
            int gr = row0 + m;
            if (gr < B) {
                float w0 = p[i][0] + bb0;
                float w1 = p[i][1] + bb1;
                float w2 = p[i][2] + bb2;
                float mean = 0.5f * (w0 + w1);
                float dd   = 0.5f * (w0 - w1);
                float rad  = sqrtf(dd*dd + w2*w2);
                out[(size_t)gr*2 + 0] = mean - rad;
                out[(size_t)gr*2 + 1] = mean + rad;
            }
        }
    }
}

extern "C" void kernel_launch(void* const* d_in, const int* in_sizes, int n_in,
                              void* d_out, int out_size)
{
    const float* x  = (const float*)d_in[0];
    const float* W1 = (const float*)d_in[1];
    const float* b1 = (const float*)d_in[2];
    const float* W2 = (const float*)d_in[3];
    const float* b2 = (const float*)d_in[4];
    const float* W3 = (const float*)d_in[5];
    const float* b3 = (const float*)d_in[6];
    float* out = (float*)d_out;

    int B = in_sizes[0] / 9;
    int grid = (B + TM - 1) / TM;

    cudaFuncSetAttribute(nn_adiab_kernel,
                         cudaFuncAttributeMaxDynamicSharedMemorySize, SMEM_BYTES);
    nn_adiab_kernel<<<grid, NTHREADS, SMEM_BYTES>>>(x, W1, b1, W2, b2, W3, b3, out, B);
}

// round 5
// speedup vs baseline: 1.8577x; 1.8577x over previous
#include <cuda_runtime.h>
#include <cuda_bf16.h>
#include <cstdint>
#include <math.h>

#define NTHREADS 512
#define TM 128

// ---------------- global scratch: W2^T split into bf16 hi/lo ----------------
__device__ __align__(128) __nv_bfloat16 g_w2t_hi[256 * 256];  // [n][k]
__device__ __align__(128) __nv_bfloat16 g_w2t_lo[256 * 256];  // [n][k]

// ---------------- smem layout (bytes) ----------------
// A (h1 split): [128 m][264 k] bf16, row stride 528B  (bank map 4g+t: conflict-free)
#define A_STRIDE 528
#define OFF_AHI  0
#define OFF_ALO  (128 * A_STRIDE)                 // 67584
#define OFF_B0   (2 * 128 * A_STRIDE)             // 135168
// B chunk: [256 n][40 k] bf16, row stride 80B (bank map 20g+t: conflict-free)
#define BMAT     (256 * 80)                       // 20480
#define OFF_BUF(b, m) (OFF_B0 + ((b) * 2 + (m)) * BMAT)
#define OFF_MISC (OFF_B0 + 4 * BMAT)              // 217088
#define OFF_W1S  OFF_MISC
#define OFF_B1S  (OFF_W1S + 768 * 4)
#define OFF_B2S  (OFF_B1S + 256 * 4)
#define OFF_W3S  (OFF_B2S + 256 * 4)
#define OFF_B3S  (OFF_W3S + 768 * 4)
#define OFF_RS   (OFF_B3S + 16)
#define SMEM_BYTES (OFF_RS + 384 * 4)             // 226832 <= 232448
#define OFF_PSUM OFF_B0                           // reuse B region post-mainloop
#define OFF_XS   OFF_AHI                          // x staged in A region pre-fill

__device__ __forceinline__ uint32_t smem_u32(const void* p) {
    uint32_t a;
    asm("{ .reg .u64 t; cvta.to.shared.u64 t, %1; cvt.u32.u64 %0, t; }" : "=r"(a) : "l"(p));
    return a;
}

#define MMA_BF16(acc, A, b0, b1)                                              \
    asm volatile(                                                             \
        "mma.sync.aligned.m16n8k16.row.col.f32.bf16.bf16.f32 "                \
        "{%0,%1,%2,%3}, {%4,%5,%6,%7}, {%8,%9}, {%0,%1,%2,%3};"               \
        : "+f"((acc)[0]), "+f"((acc)[1]), "+f"((acc)[2]), "+f"((acc)[3])      \
        : "r"((A)[0]), "r"((A)[1]), "r"((A)[2]), "r"((A)[3]),                 \
          "r"(b0), "r"(b1))

__device__ __forceinline__ void split_pack(float v0, float v1, uint32_t& hi, uint32_t& lo) {
    __nv_bfloat16 h0 = __float2bfloat16_rn(v0);
    __nv_bfloat16 h1 = __float2bfloat16_rn(v1);
    float h0f = __bfloat162float(h0), h1f = __bfloat162float(h1);
    __nv_bfloat162 hp; hp.x = h0; hp.y = h1;
    __nv_bfloat162 lp = __floats2bfloat162_rn(v0 - h0f, v1 - h1f);
    hi = *(uint32_t*)&hp;
    lo = *(uint32_t*)&lp;
}

// ---------------- kernel 1: transpose + split W2 ----------------
__global__ void prep_w2(const float* __restrict__ W2) {
    __shared__ float tile[32][33];
    int bx = blockIdx.x & 7;        // n tile
    int by = blockIdx.x >> 3;       // k tile
    int tx = threadIdx.x & 31;
    int ty = threadIdx.x >> 5;      // 0..7
    #pragma unroll
    for (int i = 0; i < 32; i += 8)
        tile[ty + i][tx] = W2[(by * 32 + ty + i) * 256 + bx * 32 + tx];
    __syncthreads();
    #pragma unroll
    for (int i = 0; i < 32; i += 8) {
        int n = bx * 32 + ty + i;
        int k = by * 32 + tx;
        float v = tile[tx][ty + i];     // W2[k][n]
        __nv_bfloat16 h = __float2bfloat16_rn(v);
        g_w2t_hi[n * 256 + k] = h;
        g_w2t_lo[n * 256 + k] = __float2bfloat16_rn(v - __bfloat162float(h));
    }
}

// ---------------- kernel 2: fused main ----------------
__global__ __launch_bounds__(NTHREADS, 1)
void nn_adiab_mma(const float* __restrict__ x,
                  const float* __restrict__ W1,
                  const float* __restrict__ b1,
                  const float* __restrict__ b2,
                  const float* __restrict__ W3,
                  const float* __restrict__ b3,
                  float* __restrict__ out,
                  int B)
{
    extern __shared__ __align__(128) char smem_raw[];
    const int tid  = threadIdx.x;
    const int wid  = tid >> 5;
    const int lane = tid & 31;
    const int g    = lane >> 2;     // group id 0..7
    const int t    = lane & 3;      // thread-in-group
    const int wy   = wid & 3;       // m warp coord
    const int wx   = wid >> 2;      // n warp coord
    const int m0   = wy * 32;
    const int n0   = wx * 64;
    const int row0 = blockIdx.x * TM;

    const char* ghi = (const char*)g_w2t_hi;
    const char* glo = (const char*)g_w2t_lo;

    // ---- issue cp.async for B chunk 0 immediately ----
    {
        #pragma unroll
        for (int j = 0; j < 4; j++) {
            int trans = j * NTHREADS + tid;
            int mat = trans >> 10;
            int wi  = trans & 1023;
            int n   = wi >> 2;
            int seg = wi & 3;
            uint32_t dst = smem_u32(smem_raw + OFF_BUF(0, mat) + n * 80 + seg * 16);
            const char* src = (mat ? glo : ghi) + n * 512 + seg * 16;
            asm volatile("cp.async.cg.shared.global [%0], [%1], 16;" :: "r"(dst), "l"(src) : "memory");
        }
        asm volatile("cp.async.commit_group;" ::: "memory");
    }

    float* w1s = (float*)(smem_raw + OFF_W1S);
    float* b1s = (float*)(smem_raw + OFF_B1S);
    float* b2s = (float*)(smem_raw + OFF_B2S);
    float* w3s = (float*)(smem_raw + OFF_W3S);
    float* b3s = (float*)(smem_raw + OFF_B3S);
    float* rs  = (float*)(smem_raw + OFF_RS);
    float* xs  = (float*)(smem_raw + OFF_XS);

    for (int i = tid; i < 768; i += NTHREADS) w1s[i] = W1[i];
    for (int i = tid; i < 256; i += NTHREADS) { b1s[i] = b1[i]; b2s[i] = b2[i]; }
    for (int i = tid; i < 768; i += NTHREADS) w3s[i] = W3[i];
    if (tid < 3) b3s[tid] = b3[tid];
    for (int i = tid; i < TM * 9; i += NTHREADS) {
        int r = row0 + i / 9;
        xs[i] = (r < B) ? x[(size_t)row0 * 9 + i] : 0.f;
    }
    __syncthreads();

    // ---- pairwise distances ----
    if (tid < TM) {
        const float* p = xs + tid * 9;
        float ax=p[0],ay=p[1],az=p[2], bx=p[3],by=p[4],bz=p[5], cx=p[6],cy=p[7],cz=p[8];
        float d0x=ax-bx, d0y=ay-by, d0z=az-bz;
        float d1x=ax-cx, d1y=ay-cy, d1z=az-cz;
        float d2x=bx-cx, d2y=by-cy, d2z=bz-cz;
        rs[tid*3+0] = sqrtf(d0x*d0x + d0y*d0y + d0z*d0z);
        rs[tid*3+1] = sqrtf(d1x*d1x + d1y*d1y + d1z*d1z);
        rs[tid*3+2] = sqrtf(d2x*d2x + d2y*d2y + d2z*d2z);
    }
    __syncthreads();

    // ---- build A = split-bf16(h1), [128 m][264 k] hi/lo ----
    #pragma unroll 4
    for (int i = 0; i < 32; i++) {
        int flat = i * NTHREADS + tid;        // 0..16383 (k-pairs)
        int m  = flat >> 7;
        int kp = flat & 127;
        int k  = kp * 2;
        float r0 = rs[m*3+0], r1 = rs[m*3+1], r2 = rs[m*3+2];
        float v0 = fmaf(r0, w1s[k],   fmaf(r1, w1s[256+k],   fmaf(r2, w1s[512+k],   b1s[k])));
        float v1 = fmaf(r0, w1s[k+1], fmaf(r1, w1s[256+k+1], fmaf(r2, w1s[512+k+1], b1s[k+1])));
        v0 = fmaxf(v0, 0.f);
        v1 = fmaxf(v1, 0.f);
        uint32_t hi, lo; split_pack(v0, v1, hi, lo);
        uint32_t off = (uint32_t)m * A_STRIDE + (uint32_t)k * 2;
        *(uint32_t*)(smem_raw + OFF_AHI + off) = hi;
        *(uint32_t*)(smem_raw + OFF_ALO + off) = lo;
    }

    // ---- accumulators ----
    float acc[2][8][4];
    #pragma unroll
    for (int mt = 0; mt < 2; mt++)
        #pragma unroll
        for (int nt = 0; nt < 8; nt++)
            #pragma unroll
            for (int q = 0; q < 4; q++) acc[mt][nt][q] = 0.f;

    // ---- mainloop: 8 chunks of k=32, B double-buffered via cp.async ----
    for (int c = 0; c < 8; c++) {
        const int buf = c & 1;
        if (c < 7) {
            #pragma unroll
            for (int j = 0; j < 4; j++) {
                int trans = j * NTHREADS + tid;
                int mat = trans >> 10;
                int wi  = trans & 1023;
                int n   = wi >> 2;
                int seg = wi & 3;
                uint32_t dst = smem_u32(smem_raw + OFF_BUF(buf ^ 1, mat) + n * 80 + seg * 16);
                const char* src = (mat ? glo : ghi) + n * 512 + (c + 1) * 64 + seg * 16;
                asm volatile("cp.async.cg.shared.global [%0], [%1], 16;" :: "r"(dst), "l"(src) : "memory");
            }
            asm volatile("cp.async.commit_group;" ::: "memory");
            asm volatile("cp.async.wait_group 1;" ::: "memory");
        } else {
            asm volatile("cp.async.wait_group 0;" ::: "memory");
        }
        __syncthreads();

        #pragma unroll
        for (int kt = 0; kt < 2; kt++) {
            const int kb2 = (32 * c + kt * 16 + 2 * t) * 2;   // byte offset of k in A row
            uint32_t a_hi[2][4], a_lo[2][4];
            #pragma unroll
            for (int mt = 0; mt < 2; mt++) {
                const char* r0p = smem_raw + OFF_AHI + (m0 + mt * 16 + g) * A_STRIDE + kb2;
                const char* r1p = r0p + 8 * A_STRIDE;
                a_hi[mt][0] = *(const uint32_t*)(r0p);
                a_hi[mt][1] = *(const uint32_t*)(r1p);
                a_hi[mt][2] = *(const uint32_t*)(r0p + 16);
                a_hi[mt][3] = *(const uint32_t*)(r1p + 16);
                a_lo[mt][0] = *(const uint32_t*)(r0p + OFF_ALO);
                a_lo[mt][1] = *(const uint32_t*)(r1p + OFF_ALO);
                a_lo[mt][2] = *(const uint32_t*)(r0p + OFF_ALO + 16);
                a_lo[mt][3] = *(const uint32_t*)(r1p + OFF_ALO + 16);
            }
            #pragma unroll
            for (int nt = 0; nt < 8; nt++) {
                const char* bp = smem_raw + OFF_BUF(buf, 0)
                                 + (n0 + nt * 8 + g) * 80 + (kt * 16 + 2 * t) * 2;
                uint32_t bh0 = *(const uint32_t*)(bp);
                uint32_t bh1 = *(const uint32_t*)(bp + 16);
                uint32_t bl0 = *(const uint32_t*)(bp + BMAT);
                uint32_t bl1 = *(const uint32_t*)(bp + BMAT + 16);
                #pragma unroll
                for (int mt = 0; mt < 2; mt++) {
                    MMA_BF16(acc[mt][nt], a_hi[mt], bh0, bh1);
                    MMA_BF16(acc[mt][nt], a_hi[mt], bl0, bl1);
                    MMA_BF16(acc[mt][nt], a_lo[mt], bh0, bh1);
                }
            }
        }
        __syncthreads();
    }

    // ---- epilogue: bias2 + relu + layer3 partials, reduce in-warp over t ----
    float* psum = (float*)(smem_raw + OFF_PSUM);   // [4 wx][128 row][3]
    #pragma unroll
    for (int mt = 0; mt < 2; mt++) {
        float p[2][3];
        p[0][0]=p[0][1]=p[0][2]=0.f;
        p[1][0]=p[1][1]=p[1][2]=0.f;
        #pragma unroll
        for (int nt = 0; nt < 8; nt++) {
            int n  = n0 + nt * 8 + 2 * t;
            int n2 = n + 1;
            float bn = b2s[n], bn2 = b2s[n2];
            float h00 = fmaxf(acc[mt][nt][0] + bn,  0.f);
            float h01 = fmaxf(acc[mt][nt][1] + bn2, 0.f);
            float h10 = fmaxf(acc[mt][nt][2] + bn,  0.f);
            float h11 = fmaxf(acc[mt][nt][3] + bn2, 0.f);
            #pragma unroll
            for (int j = 0; j < 3; j++) {
                float wA = w3s[n * 3 + j], wB = w3s[n2 * 3 + j];
                p[0][j] = fmaf(h00, wA, fmaf(h01, wB, p[0][j]));
                p[1][j] = fmaf(h10, wA, fmaf(h11, wB, p[1][j]));
            }
        }
        #pragma unroll
        for (int s = 0; s < 2; s++)
            #pragma unroll
            for (int j = 0; j < 3; j++) {
                p[s][j] += __shfl_xor_sync(0xffffffffu, p[s][j], 1);
                p[s][j] += __shfl_xor_sync(0xffffffffu, p[s][j], 2);
            }
        if (t == 0) {
            #pragma unroll
            for (int s = 0; s < 2; s++) {
                int rloc = m0 + mt * 16 + g + 8 * s;
                #pragma unroll
                for (int j = 0; j < 3; j++)
                    psum[(wx * 128 + rloc) * 3 + j] = p[s][j];
            }
        }
    }
    __syncthreads();

    // ---- final cross-warp reduce + eigen + store ----
    if (tid < TM) {
        int gr = row0 + tid;
        if (gr < B) {
            float w0 = b3s[0], w1 = b3s[1], w2 = b3s[2];
            #pragma unroll
            for (int q = 0; q < 4; q++) {
                w0 += psum[(q * 128 + tid) * 3 + 0];
                w1 += psum[(q * 128 + tid) * 3 + 1];
                w2 += psum[(q * 128 + tid) * 3 + 2];
            }
            float mean = 0.5f * (w0 + w1);
            float dd   = 0.5f * (w0 - w1);
            float rad  = sqrtf(dd * dd + w2 * w2);
            out[(size_t)gr * 2 + 0] = mean - rad;
            out[(size_t)gr * 2 + 1] = mean + rad;
        }
    }
}

extern "C" void kernel_launch(void* const* d_in, const int* in_sizes, int n_in,
                              void* d_out, int out_size)
{
    const float* x  = (const float*)d_in[0];
    const float* W1 = (const float*)d_in[1];
    const float* b1 = (const float*)d_in[2];
    const float* W2 = (const float*)d_in[3];
    const float* b2 = (const float*)d_in[4];
    const float* W3 = (const float*)d_in[5];
    const float* b3 = (const float*)d_in[6];
    float* out = (float*)d_out;

    int B = in_sizes[0] / 9;
    int grid = (B + TM - 1) / TM;

    prep_w2<<<64, 256>>>(W2);

    cudaFuncSetAttribute(nn_adiab_mma,
                         cudaFuncAttributeMaxDynamicSharedMemorySize, SMEM_BYTES);
    nn_adiab_mma<<<grid, NTHREADS, SMEM_BYTES>>>(x, W1, b1, b2, W3, b3, out, B);
}